// round 2
// baseline (speedup 1.0000x reference)
#include <cuda_runtime.h>

#define NHALF 4096          // B
#define TN    8192          // 2N
#define D     128
#define INV_TAU 2.0f        // 1/0.5
#define BM    64            // tile rows/cols
#define NB    (TN / BM)     // 128 tiles per dim
#define PAD   68            // K-major row pitch (floats); 68*4 bytes = 16B-aligned, conflict-free

__device__ float g_pn[(size_t)TN * D];   // normalized rows
__device__ float g_rowsum[TN];           // sum_j exp(sim_ij) (incl. diagonal)

// ---------------------------------------------------------------------------
// 1) Normalize rows of [z_i; z_j] and zero the row-sum accumulators.
//    One warp per row; 4 floats per lane.
// ---------------------------------------------------------------------------
__global__ void normalize_kernel(const float* __restrict__ zi,
                                 const float* __restrict__ zj) {
    int warp = (blockIdx.x * blockDim.x + threadIdx.x) >> 5;
    int lane = threadIdx.x & 31;
    if (warp >= TN) return;
    const float* src = (warp < NHALF) ? (zi + (size_t)warp * D)
                                      : (zj + (size_t)(warp - NHALF) * D);
    float4 v = ((const float4*)src)[lane];
    float ss = v.x * v.x + v.y * v.y + v.z * v.z + v.w * v.w;
#pragma unroll
    for (int o = 16; o > 0; o >>= 1) ss += __shfl_xor_sync(0xffffffffu, ss, o);
    float inv = 1.0f / fmaxf(sqrtf(ss), 1e-8f);
    float4 o4 = make_float4(v.x * inv, v.y * inv, v.z * inv, v.w * inv);
    ((float4*)(g_pn + (size_t)warp * D))[lane] = o4;
    if (lane == 0) g_rowsum[warp] = 0.0f;
}

// ---------------------------------------------------------------------------
// 2) Fused sim-GEMM + exp + row/col sum. Lower-triangle tiles only (symmetry):
//    off-diagonal tile (by>bx) contributes exp() to rowsum[by-rows] (row sums)
//    AND rowsum[bx-rows] (col sums == transposed row sums). Diagonal tile
//    contributes row sums only (includes j==i term, subtracted in finalize).
//    256 threads, 4x4 register tile per thread, K=128 fully resident (K-major).
// ---------------------------------------------------------------------------
__global__ __launch_bounds__(256) void simgemm_kernel() {
    int bx = blockIdx.x, by = blockIdx.y;
    if (bx > by) return;

    extern __shared__ float smem[];
    float* As   = smem;                  // [128][PAD]
    float* Bs   = smem + D * PAD;        // [128][PAD]
    float* redr = smem + 2 * D * PAD;    // [64] per-tile row sums
    float* redc = redr + 64;             // [64] per-tile col sums

    int tid = threadIdx.x;

    // ---- load both tiles K-major (coalesced gmem reads, conflict-free STS.128)
    int kk = tid & 31;   // k lane (coalesced dimension)
    int rg = tid >> 5;   // row-group 0..7
    const float* pa = g_pn + (size_t)by * BM * D;
    const float* pb = g_pn + (size_t)bx * BM * D;
#pragma unroll
    for (int ko = 0; ko < 4; ko++) {
        int k = kk + ko * 32;
#pragma unroll
        for (int gi = 0; gi < 2; gi++) {
            int g = rg + gi * 8;         // 0..15 (float4 row group)
            float4 av, bv;
            av.x = pa[(g * 4 + 0) * D + k];
            av.y = pa[(g * 4 + 1) * D + k];
            av.z = pa[(g * 4 + 2) * D + k];
            av.w = pa[(g * 4 + 3) * D + k];
            *(float4*)&As[k * PAD + g * 4] = av;
            bv.x = pb[(g * 4 + 0) * D + k];
            bv.y = pb[(g * 4 + 1) * D + k];
            bv.z = pb[(g * 4 + 2) * D + k];
            bv.w = pb[(g * 4 + 3) * D + k];
            *(float4*)&Bs[k * PAD + g * 4] = bv;
        }
    }
    if (tid < 64) redc[tid] = 0.0f;
    __syncthreads();

    // ---- 4x4 register-tile GEMM over K=128
    int tx = tid & 15, ty = tid >> 4;
    float acc[4][4] = {};
#pragma unroll 8
    for (int k = 0; k < D; k++) {
        float4 a = *(const float4*)&As[k * PAD + ty * 4];
        float4 b = *(const float4*)&Bs[k * PAD + tx * 4];
        acc[0][0] += a.x * b.x; acc[0][1] += a.x * b.y; acc[0][2] += a.x * b.z; acc[0][3] += a.x * b.w;
        acc[1][0] += a.y * b.x; acc[1][1] += a.y * b.y; acc[1][2] += a.y * b.z; acc[1][3] += a.y * b.w;
        acc[2][0] += a.z * b.x; acc[2][1] += a.z * b.y; acc[2][2] += a.z * b.z; acc[2][3] += a.z * b.w;
        acc[3][0] += a.w * b.x; acc[3][1] += a.w * b.y; acc[3][2] += a.w * b.z; acc[3][3] += a.w * b.w;
    }

    // ---- exp + per-thread row/col partial sums (no max needed: sim <= 2)
    float rs[4] = {0.f, 0.f, 0.f, 0.f}, cs[4] = {0.f, 0.f, 0.f, 0.f};
#pragma unroll
    for (int i = 0; i < 4; i++)
#pragma unroll
        for (int j = 0; j < 4; j++) {
            float e = __expf(acc[i][j] * INV_TAU);
            rs[i] += e;
            cs[j] += e;
        }

    // row reduce across the 16 tx lanes (same ty within half-warp)
#pragma unroll
    for (int o = 1; o <= 8; o <<= 1) {
#pragma unroll
        for (int i = 0; i < 4; i++) rs[i] += __shfl_xor_sync(0xffffffffu, rs[i], o);
    }
    if (tx == 0) {
#pragma unroll
        for (int i = 0; i < 4; i++) redr[ty * 4 + i] = rs[i];  // unique row per warp-half
    }
    // col reduce across the 2 ty values within the warp, then smem atomics across warps
#pragma unroll
    for (int j = 0; j < 4; j++) cs[j] += __shfl_xor_sync(0xffffffffu, cs[j], 16);
    if ((ty & 1) == 0) {
#pragma unroll
        for (int j = 0; j < 4; j++) atomicAdd(&redc[tx * 4 + j], cs[j]);
    }
    __syncthreads();

    // ---- push tile sums to global row accumulators
    if (tid < 64) {
        atomicAdd(&g_rowsum[by * BM + tid], redr[tid]);
    } else if (tid < 128 && bx != by) {
        atomicAdd(&g_rowsum[bx * BM + (tid - 64)], redc[tid - 64]);
    }
}

// ---------------------------------------------------------------------------
// 3) Finalize: per row i, S = rowsum - exp(sim_ii); loss_i = log(S) - sim_pos.
//    One warp per row; accumulate mean into *out.
// ---------------------------------------------------------------------------
__global__ void finalize_kernel(float* __restrict__ out) {
    int warp = (blockIdx.x * blockDim.x + threadIdx.x) >> 5;
    int lane = threadIdx.x & 31;
    if (warp >= TN) return;
    int pair = (warp < NHALF) ? warp + NHALF : warp - NHALF;
    float4 v = ((const float4*)(g_pn + (size_t)warp * D))[lane];
    float4 w = ((const float4*)(g_pn + (size_t)pair * D))[lane];
    float ss = v.x * v.x + v.y * v.y + v.z * v.z + v.w * v.w;
    float pd = v.x * w.x + v.y * w.y + v.z * w.z + v.w * w.w;
#pragma unroll
    for (int o = 16; o > 0; o >>= 1) {
        ss += __shfl_xor_sync(0xffffffffu, ss, o);
        pd += __shfl_xor_sync(0xffffffffu, pd, o);
    }
    if (lane == 0) {
        float S = g_rowsum[warp] - __expf(ss * INV_TAU);
        float val = logf(S) - pd * INV_TAU;
        atomicAdd(out, val * (1.0f / (float)TN));
    }
}

// ---------------------------------------------------------------------------
extern "C" void kernel_launch(void* const* d_in, const int* in_sizes, int n_in,
                              void* d_out, int out_size) {
    const float* zi = (const float*)d_in[0];
    const float* zj = (const float*)d_in[1];
    float* out = (float*)d_out;

    cudaMemsetAsync(out, 0, sizeof(float));

    normalize_kernel<<<TN / 8, 256>>>(zi, zj);

    size_t smem_bytes = (size_t)(2 * D * PAD + 128) * sizeof(float);  // ~70.1 KB
    cudaFuncSetAttribute(simgemm_kernel,
                         cudaFuncAttributeMaxDynamicSharedMemorySize,
                         (int)smem_bytes);
    dim3 grid(NB, NB);
    simgemm_kernel<<<grid, 256, smem_bytes>>>();

    finalize_kernel<<<TN / 8, 256>>>(out);
}

// round 3
// speedup vs baseline: 4.0122x; 4.0122x over previous
#include <cuda_runtime.h>
#include <cuda_bf16.h>
#include <cstdint>

#define NHALF 4096
#define TN    8192
#define D     128
#define BM    128           // CTA tile (rows == cols)
#define NB    (TN / BM)     // 64 tile blocks per dim
#define PITCH 136           // smem row pitch in bf16 (128 + 8 pad) -> stride 68 words

__device__ float         g_pn [(size_t)TN * D];   // fp32 normalized rows (pos/diag exactness)
__device__ __nv_bfloat16 g_pnh[(size_t)TN * D];   // bf16 copy for tensor-core GEMM
__device__ float         g_rowsum[TN];            // sum_{j != i} exp(sim_ij)

// ---------------------------------------------------------------------------
// 1) Normalize rows; emit fp32 + bf16 copies; zero row-sum accumulators.
// ---------------------------------------------------------------------------
__global__ void normalize_kernel(const float* __restrict__ zi,
                                 const float* __restrict__ zj) {
    int warp = (blockIdx.x * blockDim.x + threadIdx.x) >> 5;
    int lane = threadIdx.x & 31;
    if (warp >= TN) return;
    const float* src = (warp < NHALF) ? (zi + (size_t)warp * D)
                                      : (zj + (size_t)(warp - NHALF) * D);
    float4 v = ((const float4*)src)[lane];
    float ss = v.x * v.x + v.y * v.y + v.z * v.z + v.w * v.w;
#pragma unroll
    for (int o = 16; o > 0; o >>= 1) ss += __shfl_xor_sync(0xffffffffu, ss, o);
    float inv = 1.0f / fmaxf(sqrtf(ss), 1e-8f);
    float4 o4 = make_float4(v.x * inv, v.y * inv, v.z * inv, v.w * inv);
    ((float4*)(g_pn + (size_t)warp * D))[lane] = o4;
    __nv_bfloat162 h0 = __floats2bfloat162_rn(o4.x, o4.y);
    __nv_bfloat162 h1 = __floats2bfloat162_rn(o4.z, o4.w);
    uint2 u;
    u.x = *reinterpret_cast<uint32_t*>(&h0);
    u.y = *reinterpret_cast<uint32_t*>(&h1);
    ((uint2*)(g_pnh + (size_t)warp * D))[lane] = u;
    if (lane == 0) g_rowsum[warp] = 0.0f;
}

// ---------------------------------------------------------------------------
// 2) Fused bf16 HMMA sim-GEMM + exp + row/col sums over lower-triangle tiles.
//    256 threads = 8 warps (2x4), warp tile 64x32, mma.sync m16n8k16.
// ---------------------------------------------------------------------------
__device__ __forceinline__ void ldsm4(uint32_t& r0, uint32_t& r1,
                                      uint32_t& r2, uint32_t& r3, uint32_t addr) {
    asm volatile("ldmatrix.sync.aligned.m8n8.x4.shared.b16 {%0,%1,%2,%3}, [%4];"
                 : "=r"(r0), "=r"(r1), "=r"(r2), "=r"(r3) : "r"(addr));
}

__device__ __forceinline__ void mma16816(float* d, const uint32_t* a, const uint32_t* b) {
    asm volatile(
        "mma.sync.aligned.m16n8k16.row.col.f32.bf16.bf16.f32 "
        "{%0,%1,%2,%3}, {%4,%5,%6,%7}, {%8,%9}, {%0,%1,%2,%3};"
        : "+f"(d[0]), "+f"(d[1]), "+f"(d[2]), "+f"(d[3])
        : "r"(a[0]), "r"(a[1]), "r"(a[2]), "r"(a[3]), "r"(b[0]), "r"(b[1]));
}

__global__ __launch_bounds__(256, 2) void simgemm_kernel() {
    int bx = blockIdx.x, by = blockIdx.y;
    if (bx > by) return;

    extern __shared__ char smem_raw[];
    __nv_bfloat16* As = (__nv_bfloat16*)smem_raw;                       // [128][PITCH]
    __nv_bfloat16* Bs = As + BM * PITCH;                                // [128][PITCH]
    float* rsum = (float*)(Bs + BM * PITCH);                            // [128]
    float* csum = rsum + BM;                                            // [128]

    int tid = threadIdx.x, lane = tid & 31, wid = tid >> 5;

    // ---- load tiles (bf16, row-major [row][k]) -> smem, coalesced uint4
    const __nv_bfloat16* srcA = g_pnh + (size_t)by * BM * D;
    const __nv_bfloat16* srcB = g_pnh + (size_t)bx * BM * D;
#pragma unroll
    for (int it = 0; it < (BM * D) / (256 * 8); it++) {
        int e = it * 2048 + tid * 8;
        int row = e >> 7, col = e & 127;
        *(uint4*)&As[row * PITCH + col] = *(const uint4*)&srcA[e];
        *(uint4*)&Bs[row * PITCH + col] = *(const uint4*)&srcB[e];
    }
    if (tid < BM) { rsum[tid] = 0.0f; csum[tid] = 0.0f; }
    __syncthreads();

    // ---- warp tiling: 2 (M) x 4 (N) warps; warp tile 64x32
    int wm = (wid >> 2) * 64;
    int wn = (wid & 3) * 32;

    uint32_t aTile = (uint32_t)__cvta_generic_to_shared(As);
    uint32_t bTile = (uint32_t)__cvta_generic_to_shared(Bs);

    float acc[4][4][4];
#pragma unroll
    for (int mt = 0; mt < 4; mt++)
#pragma unroll
        for (int nt = 0; nt < 4; nt++)
#pragma unroll
            for (int v = 0; v < 4; v++) acc[mt][nt][v] = 0.0f;

#pragma unroll
    for (int ks = 0; ks < 8; ks++) {
        int k0 = ks * 16;
        uint32_t a[4][4], b[4][2];
        // A frags: 4 m-tiles of 16 rows
#pragma unroll
        for (int mt = 0; mt < 4; mt++) {
            int row = wm + mt * 16 + (lane & 15);
            int col = k0 + ((lane >> 4) << 3);
            ldsm4(a[mt][0], a[mt][1], a[mt][2], a[mt][3],
                  aTile + (uint32_t)(row * PITCH + col) * 2u);
        }
        // B frags: 2 ldmatrix.x4 cover 4 n-tiles of 8 rows
#pragma unroll
        for (int np = 0; np < 2; np++) {
            int g = lane >> 3;
            int row = wn + np * 16 + ((g >> 1) << 3) + (lane & 7);
            int col = k0 + ((g & 1) << 3);
            uint32_t r0, r1, r2, r3;
            ldsm4(r0, r1, r2, r3, bTile + (uint32_t)(row * PITCH + col) * 2u);
            b[np * 2 + 0][0] = r0; b[np * 2 + 0][1] = r1;
            b[np * 2 + 1][0] = r2; b[np * 2 + 1][1] = r3;
        }
#pragma unroll
        for (int mt = 0; mt < 4; mt++)
#pragma unroll
            for (int nt = 0; nt < 4; nt++)
                mma16816(acc[mt][nt], a[mt], b[nt]);
    }

    // ---- epilogue: exp (sim <= 2, no max needed), diagonal masked, partial sums
    bool diag = (bx == by);
    int r0 = lane >> 2, c0 = (lane & 3) * 2;
    float rp[8], cp[8];
#pragma unroll
    for (int i = 0; i < 8; i++) { rp[i] = 0.0f; cp[i] = 0.0f; }

#pragma unroll
    for (int mt = 0; mt < 4; mt++) {
#pragma unroll
        for (int nt = 0; nt < 4; nt++) {
            float e0 = __expf(acc[mt][nt][0] * 2.0f);
            float e1 = __expf(acc[mt][nt][1] * 2.0f);
            float e2 = __expf(acc[mt][nt][2] * 2.0f);
            float e3 = __expf(acc[mt][nt][3] * 2.0f);
            if (diag) {
                int lr = wm + mt * 16 + r0;   // local row within tile
                int lc = wn + nt * 8 + c0;    // local col within tile
                if (lr == lc)         e0 = 0.0f;
                if (lr == lc + 1)     e1 = 0.0f;
                if (lr + 8 == lc)     e2 = 0.0f;
                if (lr + 8 == lc + 1) e3 = 0.0f;
            }
            rp[mt * 2 + 0] += e0 + e1;
            rp[mt * 2 + 1] += e2 + e3;
            cp[nt * 2 + 0] += e0 + e2;
            cp[nt * 2 + 1] += e1 + e3;
        }
    }

    // row reduce across lanes sharing a row (lane%4 varies)
#pragma unroll
    for (int o = 1; o <= 2; o <<= 1)
#pragma unroll
        for (int i = 0; i < 8; i++) rp[i] += __shfl_xor_sync(0xffffffffu, rp[i], o);
    if ((lane & 3) == 0) {
#pragma unroll
        for (int mt = 0; mt < 4; mt++) {
            atomicAdd(&rsum[wm + mt * 16 + r0 + 0], rp[mt * 2 + 0]);
            atomicAdd(&rsum[wm + mt * 16 + r0 + 8], rp[mt * 2 + 1]);
        }
    }
    // col reduce across lanes sharing a col (lane>>2 varies)
#pragma unroll
    for (int o = 4; o <= 16; o <<= 1)
#pragma unroll
        for (int i = 0; i < 8; i++) cp[i] += __shfl_xor_sync(0xffffffffu, cp[i], o);
    if (lane < 4) {
#pragma unroll
        for (int nt = 0; nt < 4; nt++) {
            atomicAdd(&csum[wn + nt * 8 + lane * 2 + 0], cp[nt * 2 + 0]);
            atomicAdd(&csum[wn + nt * 8 + lane * 2 + 1], cp[nt * 2 + 1]);
        }
    }
    __syncthreads();

    // ---- one global RED per row (+ per col for off-diagonal tiles)
    if (tid < BM) {
        atomicAdd(&g_rowsum[by * BM + tid], rsum[tid]);
    } else if (!diag) {
        atomicAdd(&g_rowsum[bx * BM + (tid - BM)], csum[tid - BM]);
    }
}

// ---------------------------------------------------------------------------
// 3) Finalize: loss_i = log(rowsum_i) - pos_i/tau (diag already excluded).
//    pos computed from exact fp32 normalized rows.
// ---------------------------------------------------------------------------
__global__ void finalize_kernel(float* __restrict__ out) {
    int warp = (blockIdx.x * blockDim.x + threadIdx.x) >> 5;
    int lane = threadIdx.x & 31;
    if (warp >= TN) return;
    int pair = (warp < NHALF) ? warp + NHALF : warp - NHALF;
    float4 v = ((const float4*)(g_pn + (size_t)warp * D))[lane];
    float4 w = ((const float4*)(g_pn + (size_t)pair * D))[lane];
    float pd = v.x * w.x + v.y * w.y + v.z * w.z + v.w * w.w;
#pragma unroll
    for (int o = 16; o > 0; o >>= 1) pd += __shfl_xor_sync(0xffffffffu, pd, o);
    if (lane == 0) {
        float val = logf(g_rowsum[warp]) - pd * 2.0f;
        atomicAdd(out, val * (1.0f / (float)TN));
    }
}

// ---------------------------------------------------------------------------
extern "C" void kernel_launch(void* const* d_in, const int* in_sizes, int n_in,
                              void* d_out, int out_size) {
    const float* zi = (const float*)d_in[0];
    const float* zj = (const float*)d_in[1];
    float* out = (float*)d_out;

    cudaMemsetAsync(out, 0, sizeof(float));

    normalize_kernel<<<TN / 8, 256>>>(zi, zj);

    size_t smem_bytes = (size_t)(2 * BM * PITCH) * sizeof(__nv_bfloat16)
                        + 2 * BM * sizeof(float);   // ~70.7 KB
    static bool attr_set = false;
    if (!attr_set) {
        cudaFuncSetAttribute(simgemm_kernel,
                             cudaFuncAttributeMaxDynamicSharedMemorySize,
                             (int)smem_bytes);
        attr_set = true;
    }
    dim3 grid(NB, NB);
    simgemm_kernel<<<grid, 256, smem_bytes>>>();

    finalize_kernel<<<TN / 8, 256>>>(out);
}